// round 2
// baseline (speedup 1.0000x reference)
#include <cuda_runtime.h>

// Problem dims
#define N_DIM  8192
#define IN_CH  128
#define OUT_CH 64

// Big-GEMM tiling
#define TM       128
#define KB       32
#define SPLITK   8
#define KSPAN    (N_DIM / SPLITK)   // 1024
#define NTHREADS 128

// Scratch (allocation-free rule: __device__ globals)
__device__ float g_tr[N_DIM * OUT_CH];                 // features @ W
__device__ float g_sp[N_DIM * OUT_CH];                 // filt * (wavelets_inv @ g_tr)
__device__ float g_part[SPLITK * N_DIM * OUT_CH];      // split-K partials (16 MB)

// ---- packed f32x2 helpers (FFMA2: 2 FMAs / instruction) ----
__device__ __forceinline__ void fma2(unsigned long long& c,
                                     unsigned long long a,
                                     unsigned long long b) {
    asm volatile("fma.rn.f32x2 %0, %1, %2, %0;" : "+l"(c) : "l"(a), "l"(b));
}
__device__ __forceinline__ unsigned long long dup2(float x) {
    unsigned long long r;
    asm("mov.b64 %0, {%1, %1};" : "=l"(r) : "f"(x));
    return r;
}
__device__ __forceinline__ void unpack2(unsigned long long v, float& lo, float& hi) {
    asm("mov.b64 {%0, %1}, %2;" : "=f"(lo), "=f"(hi) : "l"(v));
}

// ---------------------------------------------------------------------------
// Kernel 1: g_tr = features @ W      [8192,128] @ [128,64]
// ---------------------------------------------------------------------------
__global__ __launch_bounds__(256) void lin_kernel(
    const float* __restrict__ F, const float* __restrict__ W)
{
    __shared__ float Ws[IN_CH][OUT_CH];   // 32 KB

    const int tid = threadIdx.x;
    // load W: 8192 floats = 2048 float4 / 256 threads = 8 each
    #pragma unroll
    for (int t = 0; t < 8; t++) {
        int idx = tid + t * 256;          // float4 index
        int r = idx >> 4;                 // row (16 float4 per row)
        int c4 = idx & 15;
        *reinterpret_cast<float4*>(&Ws[r][c4 * 4]) =
            *reinterpret_cast<const float4*>(&W[r * OUT_CH + c4 * 4]);
    }
    __syncthreads();

    const int row = blockIdx.x * 32 + (tid >> 3);   // 32 rows per block
    const int c0  = (tid & 7) * 8;                  // 8 cols per thread

    float acc[8];
    #pragma unroll
    for (int j = 0; j < 8; j++) acc[j] = 0.0f;

    #pragma unroll 8
    for (int k = 0; k < IN_CH; k += 4) {
        float4 a4 = *reinterpret_cast<const float4*>(&F[row * IN_CH + k]);
        float av[4] = {a4.x, a4.y, a4.z, a4.w};
        #pragma unroll
        for (int kk = 0; kk < 4; kk++) {
            #pragma unroll
            for (int j = 0; j < 8; j++)
                acc[j] = fmaf(av[kk], Ws[k + kk][c0 + j], acc[j]);
        }
    }
    #pragma unroll
    for (int j = 0; j < 8; j++) g_tr[row * OUT_CH + c0 + j] = acc[j];
}

// ---------------------------------------------------------------------------
// Kernel 2: big GEMM  P[s] += A[:, kspan_s] @ B[kspan_s, :]
//   A: [8192, 8192] row-major (wavelets_inv or wavelets)
//   B: g_tr (phase 0) or g_sp (phase 1), [8192, 64]
//   Per-thread register tile: 8 rows x 8 cols, accumulated as f32x2 pairs
//   along columns (col pairs are contiguous in B -> natural ld.shared.b64).
// ---------------------------------------------------------------------------
__global__ __launch_bounds__(NTHREADS, 4) void big_gemm(
    const float* __restrict__ A, int phase)
{
    __shared__ float As[TM][KB + 1];      // 128 x 33 (+1 pad: conflict-free)
    __shared__ float Bs[KB][OUT_CH];      // 32 x 64

    const float* __restrict__ Bm = phase ? g_sp : g_tr;

    const int tid   = threadIdx.x;
    const int mBase = blockIdx.x * TM;
    const int kBase = blockIdx.y * KSPAN;

    const int colg = tid & 7;             // 8 col-groups  -> cols colg*8 .. +7
    const int rowg = tid >> 3;            // 16 row-groups -> rows rowg*8 .. +7

    unsigned long long acc[8][4];
    #pragma unroll
    for (int i = 0; i < 8; i++)
        #pragma unroll
        for (int j = 0; j < 4; j++) acc[i][j] = 0ull;

    for (int kc = 0; kc < KSPAN; kc += KB) {
        // ---- load A tile: 128x32 floats = 1024 float4, 8 per thread ----
        #pragma unroll
        for (int t = 0; t < 8; t++) {
            int idx = tid + t * NTHREADS;           // 0..1023
            int r   = idx >> 3;                     // row 0..127
            int kq  = idx & 7;                      // float4 within row
            float4 v = *reinterpret_cast<const float4*>(
                &A[(size_t)(mBase + r) * N_DIM + (kBase + kc + kq * 4)]);
            As[r][kq * 4 + 0] = v.x;
            As[r][kq * 4 + 1] = v.y;
            As[r][kq * 4 + 2] = v.z;
            As[r][kq * 4 + 3] = v.w;
        }
        // ---- load B tile: 32x64 floats = 512 float4, 4 per thread ----
        #pragma unroll
        for (int t = 0; t < 4; t++) {
            int idx = tid + t * NTHREADS;           // 0..511
            int r   = idx >> 4;                     // k-row 0..31
            int c4  = idx & 15;
            *reinterpret_cast<float4*>(&Bs[r][c4 * 4]) =
                *reinterpret_cast<const float4*>(
                    &Bm[(size_t)(kBase + kc + r) * OUT_CH + c4 * 4]);
        }
        __syncthreads();

        #pragma unroll 8
        for (int kk = 0; kk < KB; kk++) {
            unsigned long long bfrag[4];
            #pragma unroll
            for (int j = 0; j < 4; j++)
                bfrag[j] = *reinterpret_cast<const unsigned long long*>(
                    &Bs[kk][colg * 8 + j * 2]);
            #pragma unroll
            for (int i = 0; i < 8; i++) {
                unsigned long long ad = dup2(As[rowg * 8 + i][kk]);
                #pragma unroll
                for (int j = 0; j < 4; j++)
                    fma2(acc[i][j], ad, bfrag[j]);
            }
        }
        __syncthreads();
    }

    // ---- write partials: 8 cols contiguous per row -> 2 x STG.128 ----
    float* pOut = g_part + (size_t)blockIdx.y * (N_DIM * OUT_CH);
    #pragma unroll
    for (int i = 0; i < 8; i++) {
        int row = mBase + rowg * 8 + i;
        float4 v0, v1;
        unpack2(acc[i][0], v0.x, v0.y);
        unpack2(acc[i][1], v0.z, v0.w);
        unpack2(acc[i][2], v1.x, v1.y);
        unpack2(acc[i][3], v1.z, v1.w);
        float* dst = &pOut[(size_t)row * OUT_CH + colg * 8];
        *reinterpret_cast<float4*>(dst)     = v0;
        *reinterpret_cast<float4*>(dst + 4) = v1;
    }
}

// ---------------------------------------------------------------------------
// Kernel 3: reduce split-K partials.
//   phase 0: g_sp  = filt[m] * sum_s P[s]      (row scaling folded in)
//   phase 1: d_out = sum_s P[s]
// ---------------------------------------------------------------------------
__global__ __launch_bounds__(256) void reduce_kernel(
    const float* __restrict__ filt, float* __restrict__ outp, int phase)
{
    const int i = blockIdx.x * blockDim.x + threadIdx.x;  // float4 index
    const int stride4 = (N_DIM * OUT_CH) / 4;             // 131072
    const float4* P = reinterpret_cast<const float4*>(g_part);

    float4 s = P[i];
    #pragma unroll
    for (int sp = 1; sp < SPLITK; sp++) {
        float4 v = P[i + sp * stride4];
        s.x += v.x; s.y += v.y; s.z += v.z; s.w += v.w;
    }

    if (phase == 0) {
        int m = (i * 4) / OUT_CH;     // OUT_CH % 4 == 0 -> constant within float4
        float f = filt[m];
        s.x *= f; s.y *= f; s.z *= f; s.w *= f;
        reinterpret_cast<float4*>(g_sp)[i] = s;
    } else {
        reinterpret_cast<float4*>(outp)[i] = s;
    }
}

// ---------------------------------------------------------------------------
// Launch:  inputs (metadata order): features, weight_matrix, filt,
//          wavelets, wavelets_inv.  Output: float [8192, 64].
// ---------------------------------------------------------------------------
extern "C" void kernel_launch(void* const* d_in, const int* in_sizes, int n_in,
                              void* d_out, int out_size)
{
    const float* features     = (const float*)d_in[0];
    const float* weight       = (const float*)d_in[1];
    const float* filt         = (const float*)d_in[2];
    const float* wavelets     = (const float*)d_in[3];
    const float* wavelets_inv = (const float*)d_in[4];
    float* out = (float*)d_out;

    // 1) g_tr = features @ W
    lin_kernel<<<N_DIM / 32, 256>>>(features, weight);

    // 2) partials = wavelets_inv @ g_tr  (split-K)
    dim3 grid(N_DIM / TM, SPLITK);
    big_gemm<<<grid, NTHREADS>>>(wavelets_inv, 0);

    // 3) g_sp = filt[:,None] * sum(partials)
    reduce_kernel<<<(N_DIM * OUT_CH) / 4 / 256, 256>>>(filt, nullptr, 0);

    // 4) partials = wavelets @ g_sp  (split-K)
    big_gemm<<<grid, NTHREADS>>>(wavelets, 1);

    // 5) out = sum(partials)
    reduce_kernel<<<(N_DIM * OUT_CH) / 4 / 256, 256>>>(filt, out, 1);
}

// round 6
// speedup vs baseline: 1.6624x; 1.6624x over previous
#include <cuda_runtime.h>
#include <cuda_bf16.h>
#include <cstdint>

// ---------------------------------------------------------------------------
// Problem dims
// ---------------------------------------------------------------------------
#define N_DIM  8192
#define IN_CH  128
#define OUT_CH 64

// Big-GEMM tiling (mma.sync bf16; tcgen05 not available at compute_103)
#define TM       128               // M rows per CTA
#define KB       32                // K per stage (bf16 elements)
#define SPLITK   8
#define KSPAN    (N_DIM / SPLITK)  // 1024
#define NITER    (KSPAN / KB)      // 32
#define GTHREADS 256               // 8 warps; each warp: 16 rows x 64 cols

// Static SMEM layout: padded rows (stride 80 B = 5*16 -> ldmatrix conflict-free)
#define ASTRIDE  80                // 64 B data (32 bf16) + 16 B pad
#define BSTRIDE  80
#define S_AH     0                 // 128 * 80 = 10240
#define S_AL     10240
#define S_BH     20480             // 64 * 80 = 5120
#define S_BL     25600
#define S_TOTAL  30720

// ---------------------------------------------------------------------------
// Scratch (__device__ globals: allocation-free rule). 16B-aligned for vec ld/st.
// NOTE: these symbols are referenced ONLY inside device code — never passed
// as kernel arguments from host (that was the R4/R5 bug).
// ---------------------------------------------------------------------------
__device__ __align__(16) float g_tr[N_DIM * OUT_CH];             // features @ W
__device__ __align__(16) float g_sp[N_DIM * OUT_CH];             // filt * (Winv @ g_tr)
__device__ __align__(16) float g_part[SPLITK * N_DIM * OUT_CH];  // split-K partials
__device__ __align__(16) __nv_bfloat16 g_bh[OUT_CH * N_DIM];     // B^T hi, K-major [64][8192]
__device__ __align__(16) __nv_bfloat16 g_bl[OUT_CH * N_DIM];     // B^T lo

// ---------------------------------------------------------------------------
// PTX helpers (baseline ISA: ldmatrix + mma.sync only)
// ---------------------------------------------------------------------------
__device__ __forceinline__ uint32_t smem_u32(const void* p) {
    uint32_t a;
    asm("{ .reg .u64 t; cvta.to.shared.u64 t, %1; cvt.u32.u64 %0, t; }"
        : "=r"(a) : "l"(p));
    return a;
}
__device__ __forceinline__ void ldsm4(uint32_t* r, uint32_t addr) {
    asm volatile("ldmatrix.sync.aligned.m8n8.x4.shared.b16 {%0,%1,%2,%3}, [%4];"
                 : "=r"(r[0]), "=r"(r[1]), "=r"(r[2]), "=r"(r[3]) : "r"(addr));
}
__device__ __forceinline__ void mma16816(float* c, const uint32_t* a,
                                         uint32_t b0, uint32_t b1) {
    asm volatile(
        "mma.sync.aligned.m16n8k16.row.col.f32.bf16.bf16.f32 "
        "{%0,%1,%2,%3}, {%4,%5,%6,%7}, {%8,%9}, {%0,%1,%2,%3};"
        : "+f"(c[0]), "+f"(c[1]), "+f"(c[2]), "+f"(c[3])
        : "r"(a[0]), "r"(a[1]), "r"(a[2]), "r"(a[3]), "r"(b0), "r"(b1));
}

// ---------------------------------------------------------------------------
// Kernel 1: g_tr = features @ W      [8192,128] @ [128,64]   (R2-proven)
// ---------------------------------------------------------------------------
__global__ __launch_bounds__(256) void lin_kernel(
    const float* __restrict__ F, const float* __restrict__ W)
{
    __shared__ float Ws[IN_CH][OUT_CH];
    const int tid = threadIdx.x;
    #pragma unroll
    for (int t = 0; t < 8; t++) {
        int idx = tid + t * 256;
        int r = idx >> 4, c4 = idx & 15;
        *reinterpret_cast<float4*>(&Ws[r][c4 * 4]) =
            *reinterpret_cast<const float4*>(&W[r * OUT_CH + c4 * 4]);
    }
    __syncthreads();

    const int row = blockIdx.x * 32 + (tid >> 3);
    const int c0  = (tid & 7) * 8;
    float acc[8];
    #pragma unroll
    for (int j = 0; j < 8; j++) acc[j] = 0.0f;

    #pragma unroll 8
    for (int k = 0; k < IN_CH; k += 4) {
        float4 a4 = *reinterpret_cast<const float4*>(&F[row * IN_CH + k]);
        float av[4] = {a4.x, a4.y, a4.z, a4.w};
        #pragma unroll
        for (int kk = 0; kk < 4; kk++)
            #pragma unroll
            for (int j = 0; j < 8; j++)
                acc[j] = fmaf(av[kk], Ws[k + kk][c0 + j], acc[j]);
    }
    #pragma unroll
    for (int j = 0; j < 8; j++) g_tr[row * OUT_CH + c0 + j] = acc[j];
}

// ---------------------------------------------------------------------------
// Kernel 2: split src[K,64] fp32 -> transposed K-major bf16 hi/lo.
//   which=0: src = g_tr ;  which=1: src = g_sp   (selected IN DEVICE CODE)
// ---------------------------------------------------------------------------
__global__ __launch_bounds__(256) void prep_b(int which)
{
    const float* __restrict__ src = which ? g_sp : g_tr;
    int idx = blockIdx.x * 256 + threadIdx.x;       // = n*8192 + k
    int k = idx & (N_DIM - 1);
    int n = idx >> 13;
    float v = src[k * OUT_CH + n];
    uint32_t u = __float_as_uint(v);
    float hi = __uint_as_float(u & 0xFFFF0000u);
    float lo = v - hi;
    reinterpret_cast<unsigned short*>(g_bh)[idx] = (unsigned short)(u >> 16);
    g_bl[idx] = __float2bfloat16(lo);
}

// ---------------------------------------------------------------------------
// Kernel 3: bf16-split GEMM (mma.sync.m16n8k16)
//   partial[s] = A[mTile, kspan_s] @ B^T ;  D = Ah*Bh + Ah*Bl + Al*Bh
// ---------------------------------------------------------------------------

// Load next chunk into registers (A: 4 float4 per thread; B: 2 uint4)
#define LDG_TILE(it_) do {                                                      \
    _Pragma("unroll")                                                           \
    for (int i_ = 0; i_ < 4; i_++)                                              \
        stA[i_] = *reinterpret_cast<const float4*>(                             \
            Ablk + (size_t)aR * N_DIM + (it_) * KB + aH * 16 + i_ * 4);         \
    _Pragma("unroll")                                                           \
    for (int i_ = 0; i_ < 2; i_++) {                                            \
        int idx_ = tid + i_ * GTHREADS;                                         \
        int c_ = idx_ & 255, row_ = c_ >> 2, q_ = c_ & 3;                       \
        const __nv_bfloat16* src_ = (idx_ >> 8) ? g_bl : g_bh;                  \
        stB[i_] = *reinterpret_cast<const uint4*>(                              \
            src_ + (size_t)row_ * N_DIM + kBase + (it_) * KB + q_ * 8);         \
    }                                                                           \
} while (0)

// Convert staged regs and store to SMEM (padded rows, no swizzle)
#define STS_TILE() do {                                                         \
    _Pragma("unroll")                                                           \
    for (int i_ = 0; i_ < 4; i_++) {                                            \
        float4 v_ = stA[i_];                                                    \
        uint32_t u0_ = __float_as_uint(v_.x), u1_ = __float_as_uint(v_.y);      \
        uint32_t u2_ = __float_as_uint(v_.z), u3_ = __float_as_uint(v_.w);      \
        uint32_t h01_, h23_;                                                    \
        asm("prmt.b32 %0, %1, %2, 0x7632;" : "=r"(h01_) : "r"(u0_), "r"(u1_));  \
        asm("prmt.b32 %0, %1, %2, 0x7632;" : "=r"(h23_) : "r"(u2_), "r"(u3_));  \
        float l0_ = v_.x - __uint_as_float(u0_ & 0xFFFF0000u);                  \
        float l1_ = v_.y - __uint_as_float(u1_ & 0xFFFF0000u);                  \
        float l2_ = v_.z - __uint_as_float(u2_ & 0xFFFF0000u);                  \
        float l3_ = v_.w - __uint_as_float(u3_ & 0xFFFF0000u);                  \
        uint32_t lo01_, lo23_;                                                  \
        asm("cvt.rn.bf16x2.f32 %0, %1, %2;" : "=r"(lo01_) : "f"(l1_), "f"(l0_));\
        asm("cvt.rn.bf16x2.f32 %0, %1, %2;" : "=r"(lo23_) : "f"(l3_), "f"(l2_));\
        uint32_t off_ = (uint32_t)aR * ASTRIDE + aH * 32 + i_ * 8;              \
        *reinterpret_cast<uint2*>(sm + S_AH + off_) = make_uint2(h01_, h23_);   \
        *reinterpret_cast<uint2*>(sm + S_AL + off_) = make_uint2(lo01_, lo23_); \
    }                                                                           \
    _Pragma("unroll")                                                           \
    for (int i_ = 0; i_ < 2; i_++) {                                            \
        int idx_ = tid + i_ * GTHREADS;                                         \
        int c_ = idx_ & 255, row_ = c_ >> 2, q_ = c_ & 3;                       \
        char* b_ = (idx_ >> 8) ? (sm + S_BL) : (sm + S_BH);                     \
        *reinterpret_cast<uint4*>(b_ + row_ * BSTRIDE + q_ * 16) = stB[i_];     \
    }                                                                           \
} while (0)

__global__ __launch_bounds__(GTHREADS) void mma_gemm(const float* __restrict__ A)
{
    __shared__ __align__(128) char sm[S_TOTAL];
    const uint32_t sbase = smem_u32(sm);

    const int tid = threadIdx.x;
    const int wid = tid >> 5;
    const int lid = tid & 31;
    const int wm  = wid * 16;                 // warp's 16-row slice

    const int mBase = blockIdx.x * TM;
    const int kBase = blockIdx.y * KSPAN;
    const float* Ablk = A + (size_t)mBase * N_DIM + kBase;

    // A staging coords: row = tid>>1, half = tid&1 -> 16 consecutive floats
    const int aR = tid >> 1;
    const int aH = tid & 1;
    float4 stA[4];
    uint4  stB[2];

    float acc[8][4];
    #pragma unroll
    for (int t = 0; t < 8; t++)
        #pragma unroll
        for (int j = 0; j < 4; j++) acc[t][j] = 0.0f;

    // per-lane ldmatrix base addresses (byte term added per k-step)
    //   A x4: lanes 0-15 -> rows (lid&15), +0B ; lanes 16-31 -> rows, +16B
    const uint32_t aAddr0 = sbase + S_AH +
        (uint32_t)(wm + (lid & 15)) * ASTRIDE + (uint32_t)((lid >> 4) << 4);
    //   B x4: lanes 0-7 n0-7 +0 ; 8-15 n0-7 +16 ; 16-23 n8-15 +0 ; 24-31 n8-15 +16
    const uint32_t rBL    = (uint32_t)((lid & 7) + ((lid >> 4) & 1) * 8);
    const uint32_t bByteL = (uint32_t)(((lid >> 3) & 1) * 16);

    LDG_TILE(0);

    for (int it = 0; it < NITER; it++) {
        if (it > 0) __syncthreads();          // prior compute done -> safe to overwrite
        STS_TILE();
        __syncthreads();                      // stage visible
        if (it + 1 < NITER) LDG_TILE(it + 1); // LDGs fly during compute

        #pragma unroll
        for (int ks = 0; ks < 2; ks++) {
            const uint32_t kByte = (uint32_t)ks * 32;
            uint32_t ah[4], al[4];
            ldsm4(ah, aAddr0 + kByte);
            ldsm4(al, aAddr0 + kByte + (S_AL - S_AH));
            #pragma unroll
            for (int np = 0; np < 4; np++) {
                uint32_t rB = (uint32_t)np * 16 + rBL;
                uint32_t bAddr = sbase + S_BH + rB * BSTRIDE + bByteL + kByte;
                uint32_t bh[4], bl[4];
                ldsm4(bh, bAddr);
                ldsm4(bl, bAddr + (S_BL - S_BH));
                float* c0 = acc[np * 2];
                float* c1 = acc[np * 2 + 1];
                mma16816(c0, ah, bh[0], bh[1]);
                mma16816(c0, ah, bl[0], bl[1]);
                mma16816(c0, al, bh[0], bh[1]);
                mma16816(c1, ah, bh[2], bh[3]);
                mma16816(c1, ah, bl[2], bl[3]);
                mma16816(c1, al, bh[2], bh[3]);
            }
        }
    }

    // epilogue: c-fragment (row = lid>>2 (+8), col = (lid&3)*2 (+1))
    const int g  = lid >> 2;
    const int tg = lid & 3;
    float* part = g_part + (size_t)blockIdx.y * (N_DIM * OUT_CH);
    const int row0 = mBase + wm + g;
    #pragma unroll
    for (int t = 0; t < 8; t++) {
        int col = t * 8 + tg * 2;
        *reinterpret_cast<float2*>(&part[(size_t)row0 * OUT_CH + col]) =
            make_float2(acc[t][0], acc[t][1]);
        *reinterpret_cast<float2*>(&part[(size_t)(row0 + 8) * OUT_CH + col]) =
            make_float2(acc[t][2], acc[t][3]);
    }
}

// ---------------------------------------------------------------------------
// Kernel 4: reduce split-K partials.
//   phase 0: g_sp = filt[m] * sum_s P[s]     phase 1: d_out = sum_s P[s]
// ---------------------------------------------------------------------------
__global__ __launch_bounds__(256) void reduce_kernel(
    const float* __restrict__ filt, float* __restrict__ outp, int phase)
{
    const int i = blockIdx.x * blockDim.x + threadIdx.x;
    const int stride4 = (N_DIM * OUT_CH) / 4;
    const float4* P = reinterpret_cast<const float4*>(g_part);

    float4 s = P[i];
    #pragma unroll
    for (int sp = 1; sp < SPLITK; sp++) {
        float4 v = P[i + sp * stride4];
        s.x += v.x; s.y += v.y; s.z += v.z; s.w += v.w;
    }
    if (phase == 0) {
        int m = (i * 4) / OUT_CH;
        float f = filt[m];
        s.x *= f; s.y *= f; s.z *= f; s.w *= f;
        reinterpret_cast<float4*>(g_sp)[i] = s;
    } else {
        reinterpret_cast<float4*>(outp)[i] = s;
    }
}

// ---------------------------------------------------------------------------
// Launch. Inputs: features, weight_matrix, filt, wavelets, wavelets_inv.
// No dynamic smem, no attributes, no static state, no device symbols as args.
// ---------------------------------------------------------------------------
extern "C" void kernel_launch(void* const* d_in, const int* in_sizes, int n_in,
                              void* d_out, int out_size)
{
    const float* features     = (const float*)d_in[0];
    const float* weight       = (const float*)d_in[1];
    const float* filt         = (const float*)d_in[2];
    const float* wavelets     = (const float*)d_in[3];
    const float* wavelets_inv = (const float*)d_in[4];
    float* out = (float*)d_out;

    dim3 grid(N_DIM / TM, SPLITK);                      // (64, 8)
    const int prepBlocks = (N_DIM * OUT_CH) / 256;      // 2048
    const int redBlocks  = (N_DIM * OUT_CH) / 4 / 256;  // 512

    // 1) g_tr = features @ W
    lin_kernel<<<N_DIM / 32, 256>>>(features, weight);
    // 2) split+transpose g_tr -> g_bh/g_bl
    prep_b<<<prepBlocks, 256>>>(0);
    // 3) partials = wavelets_inv @ g_tr
    mma_gemm<<<grid, GTHREADS>>>(wavelets_inv);
    // 4) g_sp = filt[:,None] * sum(partials)
    reduce_kernel<<<redBlocks, 256>>>(filt, nullptr, 0);
    // 5) split+transpose g_sp
    prep_b<<<prepBlocks, 256>>>(1);
    // 6) partials = wavelets @ g_sp
    mma_gemm<<<grid, GTHREADS>>>(wavelets);
    // 7) out = sum(partials)
    reduce_kernel<<<redBlocks, 256>>>(filt, out, 1);
}